// round 14
// baseline (speedup 1.0000x reference)
#include <cuda_runtime.h>
#include <cuda_fp16.h>
#include <cstdint>

#define MM 16
#define KK 8192
#define NN 8192
#define GROUPK 128
#define SPLITK 16
#define KC     512             // k per block (= KPER)
#define NTILE  128             // columns per block (4 warps x 32 cols)
#define WARPS  4
#define NTHREADS (WARPS * 32)
#define NCB    (NN / NTILE)    // 64 column-blocks
#define ROUNDS (KC / 32)       // 16 rounds of 32-k
#define SCSTRIDE  (NN / 4)     // float4 units per scale-group row
#define DEPTH  6               // cp.async rounds in flight
#define NSLOT  8               // smem ring slots (power of 2 >= DEPTH+1)

// x pre-converted to fp16 in A-fragment order: [ks*16+r][j][lane] uint4
__device__ uint4 g_xfrag[256 * 2 * 32];             // 256 KB

__device__ __forceinline__ uint32_t lop3_ea(uint32_t v, uint32_t m, uint32_t o) {
    uint32_t h;
    asm("lop3.b32 %0, %1, %2, %3, 0xEA;" : "=r"(h) : "r"(v), "r"(m), "r"(o));
    return h;   // (v & m) | o
}

__device__ __forceinline__ uint32_t packh2(float a, float b) {
    half2 h = __floats2half2_rn(a, b);
    return *reinterpret_cast<uint32_t*>(&h);
}

__device__ __forceinline__ void mma16816(float* c,
                                         uint32_t a0, uint32_t a1, uint32_t a2, uint32_t a3,
                                         uint32_t b0, uint32_t b1) {
    asm volatile(
        "mma.sync.aligned.m16n8k16.row.col.f32.f16.f16.f32 "
        "{%0,%1,%2,%3}, {%4,%5,%6,%7}, {%8,%9}, {%0,%1,%2,%3};\n"
        : "+f"(c[0]), "+f"(c[1]), "+f"(c[2]), "+f"(c[3])
        : "r"(a0), "r"(a1), "r"(a2), "r"(a3), "r"(b0), "r"(b1));
}

// Marlin-mask dequant: pairs (0,4)/(2,6) via 0x000F000F -> (h-1032);
// pairs (1,5)/(3,7) via 0x00F000F0 (=1024+16n) -> fma(h,1/16,-72) = n-8 EXACT.
// Then fp16 scale multiply (single rounding = reference w). 1 SHF instead of 3.
__device__ __forceinline__ void procj(float* acc, uint32_t wj, half2 s,
                                      const uint4& va, const uint4& vb,
                                      half2 c1032, half2 rcp16, half2 cm72) {
    uint32_t t = wj >> 8;
    uint32_t h00 = lop3_ea(wj, 0x000F000Fu, 0x64006400u);   // (n0,n4): 1024+n
    uint32_t h01 = lop3_ea(wj, 0x00F000F0u, 0x64006400u);   // (n1,n5): 1024+16n
    uint32_t h02 = lop3_ea(t,  0x000F000Fu, 0x64006400u);   // (n2,n6)
    uint32_t h03 = lop3_ea(t,  0x00F000F0u, 0x64006400u);   // (n3,n7)
    half2 w00 = __hsub2(*reinterpret_cast<half2*>(&h00), c1032);
    half2 w01 = __hfma2(*reinterpret_cast<half2*>(&h01), rcp16, cm72);
    half2 w02 = __hsub2(*reinterpret_cast<half2*>(&h02), c1032);
    half2 w03 = __hfma2(*reinterpret_cast<half2*>(&h03), rcp16, cm72);
    half2 b00 = __hmul2(w00, s), b01 = __hmul2(w01, s);
    half2 b02 = __hmul2(w02, s), b03 = __hmul2(w03, s);
    mma16816(acc, va.x, va.y, va.z, va.w,
             *reinterpret_cast<uint32_t*>(&b00), *reinterpret_cast<uint32_t*>(&b01));
    mma16816(acc, vb.x, vb.y, vb.z, vb.w,
             *reinterpret_cast<uint32_t*>(&b02), *reinterpret_cast<uint32_t*>(&b03));
}

// no-return vectorized f32 reduction into global (sm_90+)
__device__ __forceinline__ void redg_v4(float* p, float a, float b, float c, float d) {
    asm volatile("red.global.add.v4.f32 [%0], {%1, %2, %3, %4};"
                 :: "l"(p), "f"(a), "f"(b), "f"(c), "f"(d) : "memory");
}

__device__ __forceinline__ void cpasync16(uint32_t saddr, const void* gaddr) {
    asm volatile("cp.async.cg.shared.global [%0], [%1], 16;"
                 :: "r"(saddr), "l"(gaddr) : "memory");
}
__device__ __forceinline__ void cpasync_commit() {
    asm volatile("cp.async.commit_group;" ::: "memory");
}
// constant-dispatch wait (loops fully unrolled -> n is a compile-time constant)
__device__ __forceinline__ void cpasync_wait(int n) {
    switch (n) {
    case 0: asm volatile("cp.async.wait_group 0;" ::: "memory"); break;
    case 1: asm volatile("cp.async.wait_group 1;" ::: "memory"); break;
    case 2: asm volatile("cp.async.wait_group 2;" ::: "memory"); break;
    case 3: asm volatile("cp.async.wait_group 3;" ::: "memory"); break;
    case 4: asm volatile("cp.async.wait_group 4;" ::: "memory"); break;
    default: asm volatile("cp.async.wait_group 5;" ::: "memory"); break;
    }
}

// Combo front kernel: blocks 0-31 convert x into A-fragment order;
// blocks 32-95 initialize out with broadcast f32(f16(bias)) (clears poison).
__global__ void __launch_bounds__(256)
prep_combo(const float* __restrict__ x, const float* __restrict__ bias,
           float* __restrict__ out)
{
    int tid = threadIdx.x;
    if (blockIdx.x < 32) {
        int t = blockIdx.x * 256 + tid;               // 0..8191
        int rem = t & 31;
        int rg  = t >> 5;                             // ks*16 + r
        int g   = rem >> 2;
        int ii  = rem & 3;
        int b   = rg * 32 + ii * 8;
        const float* xlo = x + (size_t)g       * KK + b;
        const float* xhi = x + (size_t)(g + 8) * KK + b;
        float4 l0 = *reinterpret_cast<const float4*>(xlo);
        float4 l1 = *reinterpret_cast<const float4*>(xlo + 4);
        float4 h0 = *reinterpret_cast<const float4*>(xhi);
        float4 h1 = *reinterpret_cast<const float4*>(xhi + 4);
        uint4 e0, e1;
        e0.x = packh2(l0.x, l1.x);   // (b+0, b+4) row g     -> a0 of mma j=0
        e0.y = packh2(h0.x, h1.x);   //            row g+8   -> a1
        e0.z = packh2(l0.y, l1.y);   // (b+1, b+5)           -> a2
        e0.w = packh2(h0.y, h1.y);   //                      -> a3
        e1.x = packh2(l0.z, l1.z);   // (b+2, b+6)           -> mma j=1
        e1.y = packh2(h0.z, h1.z);
        e1.z = packh2(l0.w, l1.w);   // (b+3, b+7)
        e1.w = packh2(h0.w, h1.w);
        g_xfrag[rg * 64 + rem]      = e0;
        g_xfrag[rg * 64 + 32 + rem] = e1;
    } else {
        // init: 16384 threads x 2 float4 = 32768 float4 = all of out
        int i = (blockIdx.x - 32) * 256 + tid;        // 0..16383
        int n4 = i & (NN / 4 - 1);                    // same column set for both rows
        const float4 bv = *reinterpret_cast<const float4*>(bias + n4 * 4);
        float4 o;
        o.x = __half2float(__float2half_rn(bv.x));    // f32(f16(bias)) as in reference
        o.y = __half2float(__float2half_rn(bv.y));
        o.z = __half2float(__float2half_rn(bv.z));
        o.w = __half2float(__float2half_rn(bv.w));
        float4* out4 = reinterpret_cast<float4*>(out);
        out4[i]         = o;
        out4[i + 16384] = o;                          // +8 rows
    }
}

// GEMM with cp.async-staged qweight (6-deep smem ring) + atomic-reduce epilogue.
// Lane (g8,i4) owns cols colbase+4*g8+{0..3} of packed row 4r+i4 (coalesced 128B
// per round); MMA group j uses col set {colbase+4n+j} (undone in epilogue
// indexing). Each thread reads back only its own cp.async data -> no barrier.
// xfrag register-prefetched d=2 (L1-resident: 112KB slices + 112KB smem fit).
__global__ void __launch_bounds__(NTHREADS, 7)
qlinear_gemm(const int* __restrict__ qweight, const float* __restrict__ scales,
             float* __restrict__ out)
{
    __shared__ uint4 qsh[NSLOT][NTHREADS];   // 16 KB ring

    const int tid  = threadIdx.x;
    const int lane = tid & 31;
    const int warp = tid >> 5;
    const int ks   = blockIdx.y;
    const int cb   = blockIdx.x;
    const int colbase = cb * NTILE + warp * 32;
    const int i4 = lane & 3;   // threadID_in_group
    const int g8 = lane >> 2;  // groupID

    const half2 c1032 = __half2half2(__ushort_as_half((unsigned short)0x6408)); // 1032.0
    const half2 rcp16 = __half2half2(__ushort_as_half((unsigned short)0x2C00)); // 1/16
    const half2 cm72  = __half2half2(__ushort_as_half((unsigned short)0xD480)); // -72.0

    // qweight: round r -> row (ks*64 + 4r + i4), cols colbase+4*g8..+3 (16B)
    const int* qbase = qweight + (size_t)(ks * 64 + i4) * NN + colbase + 4 * g8;
    // scales: group rows [ks*4 .. ks*4+3]; lane reads cols colbase+4*g8..+3 (B-frag coords)
    const float4* scp = reinterpret_cast<const float4*>(
        scales + (size_t)(ks * 4) * NN + colbase) + g8;
    // A fragments for this ks
    const uint4* xf = g_xfrag + (size_t)(ks * ROUNDS) * 64 + lane;

    const uint32_t myslot = (uint32_t)__cvta_generic_to_shared(&qsh[0][tid]);

    // prime the ring: rounds 0..DEPTH-1, one commit group each
    #pragma unroll
    for (int r = 0; r < DEPTH; ++r) {
        cpasync16(myslot + (uint32_t)(r & (NSLOT - 1)) * sizeof(uint4) * NTHREADS,
                  qbase + (size_t)r * 4 * NN);
        cpasync_commit();
    }

    float accm[4][4] = {};
    uint4 vaf[2], vbf[2];              // xfrag rolling depth-2 prefetch
    vaf[0] = xf[0];       vbf[0] = xf[32];
    vaf[1] = xf[64];      vbf[1] = xf[96];

    #pragma unroll
    for (int r4 = 0; r4 < 4; ++r4) {               // 4 scale-groups of 128 k
        half2 hs[4];
        {
            float4 sf = __ldg(scp + (size_t)r4 * SCSTRIDE);
            hs[0] = __half2half2(__float2half_rn(sf.x));
            hs[1] = __half2half2(__float2half_rn(sf.y));
            hs[2] = __half2half2(__float2half_rn(sf.z));
            hs[3] = __half2half2(__float2half_rn(sf.w));
        }
        #pragma unroll
        for (int rr = 0; rr < 4; ++rr) {           // 4 rounds = 128 k
            const int r = r4 * 4 + rr;             // compile-time constant (full unroll)
            // groups issued so far = min(DEPTH + r, ROUNDS); need group r done:
            cpasync_wait(r <= ROUNDS - 1 - DEPTH ? DEPTH - 1 : ROUNDS - 1 - r);
            uint4 w = qsh[r & (NSLOT - 1)][tid];   // own data: no barrier needed
            if (r + DEPTH < ROUNDS) {              // refill ring
                cpasync16(myslot + (uint32_t)((r + DEPTH) & (NSLOT - 1)) * sizeof(uint4) * NTHREADS,
                          qbase + (size_t)(r + DEPTH) * 4 * NN);
                cpasync_commit();
            }
            uint4 va = vaf[r & 1];
            uint4 vb = vbf[r & 1];
            if (r + 2 < ROUNDS) {                  // xfrag rolling prefetch, distance 2
                vaf[r & 1] = xf[(r + 2) * 64];
                vbf[r & 1] = xf[(r + 2) * 64 + 32];
            }
            procj(accm[0], w.x, hs[0], va, vb, c1032, rcp16, cm72);
            procj(accm[1], w.y, hs[1], va, vb, c1032, rcp16, cm72);
            procj(accm[2], w.z, hs[2], va, vb, c1032, rcp16, cm72);
            procj(accm[3], w.w, hs[3], va, vb, c1032, rcp16, cm72);
        }
    }

    // ---- atomic-reduce fp32 partials into out (bias pre-added by init).
    // group j's C col = colbase + 8*i4 + j (rows g8, g8+8); +4 for c[1]/c[3].
    {
        float* op = out + (size_t)g8 * NN + colbase + 8 * i4;
        redg_v4(op,     accm[0][0], accm[1][0], accm[2][0], accm[3][0]);
        redg_v4(op + 4, accm[0][1], accm[1][1], accm[2][1], accm[3][1]);
        float* op2 = op + (size_t)8 * NN;
        redg_v4(op2,     accm[0][2], accm[1][2], accm[2][2], accm[3][2]);
        redg_v4(op2 + 4, accm[0][3], accm[1][3], accm[2][3], accm[3][3]);
    }
}

extern "C" void kernel_launch(void* const* d_in, const int* in_sizes, int n_in,
                              void* d_out, int out_size) {
    // identify inputs by unique element counts (robust to ordering)
    const float* x = nullptr; const int* qw = nullptr;
    const float* sc = nullptr; const float* bias = nullptr;
    for (int i = 0; i < n_in; ++i) {
        switch (in_sizes[i]) {
            case MM * KK:              x    = (const float*)d_in[i]; break;  // 131072
            case (KK / 8) * NN:        qw   = (const int*)  d_in[i]; break;  // 8388608
            case (KK / GROUPK) * NN:   sc   = (const float*)d_in[i]; break;  // 524288
            case NN:                   bias = (const float*)d_in[i]; break;  // 8192
        }
    }
    float* out = (float*)d_out;

    prep_combo<<<96, 256>>>(x, bias, out);     // x-permute + out-init (bias)

    dim3 grid(NCB, SPLITK);                    // 64 x 16 = 1024 blocks, 7/SM wave
    qlinear_gemm<<<grid, NTHREADS>>>(qw, sc, out);
}

// round 15
// speedup vs baseline: 1.2664x; 1.2664x over previous
#include <cuda_runtime.h>
#include <cuda_fp16.h>
#include <cstdint>

#define MM 16
#define KK 8192
#define NN 8192
#define GROUPK 128
#define SPLITK 16
#define KC     512             // k per block (= KPER)
#define NTILE  128             // columns per block (4 warps x 32 cols)
#define WARPS  4
#define NTHREADS (WARPS * 32)
#define NCB    (NN / NTILE)    // 64 column-blocks
#define ROUNDS (KC / 32)       // 16 rounds of 32-k
#define R4STRIDE  (NN)         // int4 units between rounds (4 rows * NN ints / 4)
#define SCSTRIDE  (NN / 4)     // float4 units per scale-group row
#define PFDIST 6               // L2 prefetch distance (rounds)

// x pre-converted to fp16 in A-fragment order: [ks*16+r][j][lane] uint4
__device__ uint4 g_xfrag[256 * 2 * 32];             // 256 KB

__device__ __forceinline__ uint32_t lop3_ea(uint32_t v, uint32_t m, uint32_t o) {
    uint32_t h;
    asm("lop3.b32 %0, %1, %2, %3, 0xEA;" : "=r"(h) : "r"(v), "r"(m), "r"(o));
    return h;   // (v & m) | o
}

__device__ __forceinline__ uint32_t packh2(float a, float b) {
    half2 h = __floats2half2_rn(a, b);
    return *reinterpret_cast<uint32_t*>(&h);
}

__device__ __forceinline__ void prefetchL2(const void* p) {
    asm volatile("prefetch.global.L2 [%0];" :: "l"(p));
}

__device__ __forceinline__ void mma16816(float* c,
                                         uint32_t a0, uint32_t a1, uint32_t a2, uint32_t a3,
                                         uint32_t b0, uint32_t b1) {
    asm volatile(
        "mma.sync.aligned.m16n8k16.row.col.f32.f16.f16.f32 "
        "{%0,%1,%2,%3}, {%4,%5,%6,%7}, {%8,%9}, {%0,%1,%2,%3};\n"
        : "+f"(c[0]), "+f"(c[1]), "+f"(c[2]), "+f"(c[3])
        : "r"(a0), "r"(a1), "r"(a2), "r"(a3), "r"(b0), "r"(b1));
}

// Marlin-mask dequant: pairs (0,4)/(2,6) via 0x000F000F -> (h-1032);
// pairs (1,5)/(3,7) via 0x00F000F0 (=1024+16n) -> fma(h,1/16,-72) = n-8 EXACT.
// Then fp16 scale multiply (single rounding = reference w). 1 SHF instead of 3.
__device__ __forceinline__ void procj(float* acc, uint32_t wj, half2 s,
                                      const uint4& va, const uint4& vb,
                                      half2 c1032, half2 rcp16, half2 cm72) {
    uint32_t t = wj >> 8;
    uint32_t h00 = lop3_ea(wj, 0x000F000Fu, 0x64006400u);   // (n0,n4): 1024+n
    uint32_t h01 = lop3_ea(wj, 0x00F000F0u, 0x64006400u);   // (n1,n5): 1024+16n
    uint32_t h02 = lop3_ea(t,  0x000F000Fu, 0x64006400u);   // (n2,n6)
    uint32_t h03 = lop3_ea(t,  0x00F000F0u, 0x64006400u);   // (n3,n7)
    half2 w00 = __hsub2(*reinterpret_cast<half2*>(&h00), c1032);
    half2 w01 = __hfma2(*reinterpret_cast<half2*>(&h01), rcp16, cm72);
    half2 w02 = __hsub2(*reinterpret_cast<half2*>(&h02), c1032);
    half2 w03 = __hfma2(*reinterpret_cast<half2*>(&h03), rcp16, cm72);
    half2 b00 = __hmul2(w00, s), b01 = __hmul2(w01, s);
    half2 b02 = __hmul2(w02, s), b03 = __hmul2(w03, s);
    mma16816(acc, va.x, va.y, va.z, va.w,
             *reinterpret_cast<uint32_t*>(&b00), *reinterpret_cast<uint32_t*>(&b01));
    mma16816(acc, vb.x, vb.y, vb.z, vb.w,
             *reinterpret_cast<uint32_t*>(&b02), *reinterpret_cast<uint32_t*>(&b03));
}

// no-return vectorized f32 reduction into global (sm_90+)
__device__ __forceinline__ void redg_v4(float* p, float a, float b, float c, float d) {
    asm volatile("red.global.add.v4.f32 [%0], {%1, %2, %3, %4};"
                 :: "l"(p), "f"(a), "f"(b), "f"(c), "f"(d) : "memory");
}

// Combo front kernel: blocks 0-31 convert x into A-fragment order;
// blocks 32-95 initialize out with broadcast f32(f16(bias)) (clears poison).
__global__ void __launch_bounds__(256)
prep_combo(const float* __restrict__ x, const float* __restrict__ bias,
           float* __restrict__ out)
{
    int tid = threadIdx.x;
    if (blockIdx.x < 32) {
        int t = blockIdx.x * 256 + tid;               // 0..8191
        int rem = t & 31;
        int rg  = t >> 5;                             // ks*16 + r
        int g   = rem >> 2;
        int ii  = rem & 3;
        int b   = rg * 32 + ii * 8;
        const float* xlo = x + (size_t)g       * KK + b;
        const float* xhi = x + (size_t)(g + 8) * KK + b;
        float4 l0 = *reinterpret_cast<const float4*>(xlo);
        float4 l1 = *reinterpret_cast<const float4*>(xlo + 4);
        float4 h0 = *reinterpret_cast<const float4*>(xhi);
        float4 h1 = *reinterpret_cast<const float4*>(xhi + 4);
        uint4 e0, e1;
        e0.x = packh2(l0.x, l1.x);   // (b+0, b+4) row g     -> a0 of mma j=0
        e0.y = packh2(h0.x, h1.x);   //            row g+8   -> a1
        e0.z = packh2(l0.y, l1.y);   // (b+1, b+5)           -> a2
        e0.w = packh2(h0.y, h1.y);   //                      -> a3
        e1.x = packh2(l0.z, l1.z);   // (b+2, b+6)           -> mma j=1
        e1.y = packh2(h0.z, h1.z);
        e1.z = packh2(l0.w, l1.w);   // (b+3, b+7)
        e1.w = packh2(h0.w, h1.w);
        g_xfrag[rg * 64 + rem]      = e0;
        g_xfrag[rg * 64 + 32 + rem] = e1;
    } else {
        // init: 16384 threads x 2 float4 = 32768 float4 = all of out
        int i = (blockIdx.x - 32) * 256 + tid;        // 0..16383
        int n4 = i & (NN / 4 - 1);                    // same column set for both rows
        const float4 bv = *reinterpret_cast<const float4*>(bias + n4 * 4);
        float4 o;
        o.x = __half2float(__float2half_rn(bv.x));    // f32(f16(bias)) as in reference
        o.y = __half2float(__float2half_rn(bv.y));
        o.z = __half2float(__float2half_rn(bv.z));
        o.w = __half2float(__float2half_rn(bv.w));
        float4* out4 = reinterpret_cast<float4*>(out);
        out4[i]         = o;
        out4[i + 16384] = o;                          // +8 rows
    }
}

// Smem-free GEMM with atomic-reduce epilogue (R13 structure) + scoreboard-free
// L2 prefetch of the qweight stream at distance PFDIST. Lane (g8,i4) loads
// int4 = cols colbase+4*g8+{0..3} of packed row 4r+i4 (coalesced 128B); MMA
// group j uses col set {colbase+4n+j} (undone in epilogue indexing).
// qweight + xfrag register-prefetched rolling depth-2 (now L2/L1 hits).
__global__ void __launch_bounds__(NTHREADS, 7)
qlinear_gemm(const int* __restrict__ qweight, const float* __restrict__ scales,
             float* __restrict__ out)
{
    const int tid  = threadIdx.x;
    const int lane = tid & 31;
    const int warp = tid >> 5;
    const int ks   = blockIdx.y;
    const int cb   = blockIdx.x;
    const int colbase = cb * NTILE + warp * 32;
    const int i4 = lane & 3;   // threadID_in_group
    const int g8 = lane >> 2;  // groupID

    const half2 c1032 = __half2half2(__ushort_as_half((unsigned short)0x6408)); // 1032.0
    const half2 rcp16 = __half2half2(__ushort_as_half((unsigned short)0x2C00)); // 1/16
    const half2 cm72  = __half2half2(__ushort_as_half((unsigned short)0xD480)); // -72.0

    // qweight: packed rows [ks*64 .. ks*64+63]; lane reads row (4r+i4), cols colbase+4*g8..+3
    const int4* qp = reinterpret_cast<const int4*>(
        qweight + (size_t)(ks * 64 + i4) * NN + colbase) + g8;
    // scales: group rows [ks*4 .. ks*4+3]; lane reads cols colbase+4*g8..+3 (B-fragment coords)
    const float4* scp = reinterpret_cast<const float4*>(
        scales + (size_t)(ks * 4) * NN + colbase) + g8;
    // A fragments for this ks
    const uint4* xf = g_xfrag + (size_t)(ks * ROUNDS) * 64 + lane;

    // prime L2 prefetches for rounds 2..PFDIST+1 (no scoreboard, fire-and-forget)
    #pragma unroll
    for (int r = 2; r < PFDIST + 2; ++r)
        prefetchL2(qp + (size_t)r * R4STRIDE);

    float accm[4][4] = {};
    uint4 wqbuf[2], vaf[2], vbf[2];    // rolling depth-2 round prefetch

    wqbuf[0] = *reinterpret_cast<const uint4*>(qp);
    wqbuf[1] = *reinterpret_cast<const uint4*>(qp + R4STRIDE);
    vaf[0] = xf[0];       vbf[0] = xf[32];
    vaf[1] = xf[64];      vbf[1] = xf[96];

    #pragma unroll
    for (int r4 = 0; r4 < 4; ++r4) {               // 4 scale-groups of 128 k
        half2 hs[4];
        {
            float4 sf = __ldg(scp + (size_t)r4 * SCSTRIDE);
            hs[0] = __half2half2(__float2half_rn(sf.x));
            hs[1] = __half2half2(__float2half_rn(sf.y));
            hs[2] = __half2half2(__float2half_rn(sf.z));
            hs[3] = __half2half2(__float2half_rn(sf.w));
        }
        #pragma unroll
        for (int rr = 0; rr < 4; ++rr) {           // 4 rounds = 128 k
            int r = r4 * 4 + rr;
            uint4 w  = wqbuf[r & 1];
            uint4 va = vaf[r & 1];
            uint4 vb = vbf[r & 1];
            if (r + PFDIST + 2 < ROUNDS)           // stream-ahead L2 prefetch
                prefetchL2(qp + (size_t)(r + PFDIST + 2) * R4STRIDE);
            if (r + 2 < ROUNDS) {                  // rolling prefetch, distance 2 (L2 hits now)
                wqbuf[r & 1] = *reinterpret_cast<const uint4*>(qp + (size_t)(r + 2) * R4STRIDE);
                vaf[r & 1]   = xf[(r + 2) * 64];
                vbf[r & 1]   = xf[(r + 2) * 64 + 32];
            }
            procj(accm[0], w.x, hs[0], va, vb, c1032, rcp16, cm72);
            procj(accm[1], w.y, hs[1], va, vb, c1032, rcp16, cm72);
            procj(accm[2], w.z, hs[2], va, vb, c1032, rcp16, cm72);
            procj(accm[3], w.w, hs[3], va, vb, c1032, rcp16, cm72);
        }
    }

    // ---- atomic-reduce fp32 partials into out (bias pre-added by init).
    // group j's C col = colbase + 8*i4 + j (rows g8, g8+8); +4 for c[1]/c[3].
    {
        float* op = out + (size_t)g8 * NN + colbase + 8 * i4;
        redg_v4(op,     accm[0][0], accm[1][0], accm[2][0], accm[3][0]);
        redg_v4(op + 4, accm[0][1], accm[1][1], accm[2][1], accm[3][1]);
        float* op2 = op + (size_t)8 * NN;
        redg_v4(op2,     accm[0][2], accm[1][2], accm[2][2], accm[3][2]);
        redg_v4(op2 + 4, accm[0][3], accm[1][3], accm[2][3], accm[3][3]);
    }
}

extern "C" void kernel_launch(void* const* d_in, const int* in_sizes, int n_in,
                              void* d_out, int out_size) {
    // identify inputs by unique element counts (robust to ordering)
    const float* x = nullptr; const int* qw = nullptr;
    const float* sc = nullptr; const float* bias = nullptr;
    for (int i = 0; i < n_in; ++i) {
        switch (in_sizes[i]) {
            case MM * KK:              x    = (const float*)d_in[i]; break;  // 131072
            case (KK / 8) * NN:        qw   = (const int*)  d_in[i]; break;  // 8388608
            case (KK / GROUPK) * NN:   sc   = (const float*)d_in[i]; break;  // 524288
            case NN:                   bias = (const float*)d_in[i]; break;  // 8192
        }
    }
    float* out = (float*)d_out;

    prep_combo<<<96, 256>>>(x, bias, out);     // x-permute + out-init (bias)

    dim3 grid(NCB, SPLITK);                    // 64 x 16 = 1024 blocks, 7/SM wave
    qlinear_gemm<<<grid, NTHREADS>>>(qw, sc, out);
}

// round 16
// speedup vs baseline: 1.2937x; 1.0216x over previous
#include <cuda_runtime.h>
#include <cuda_fp16.h>
#include <cstdint>

#define MM 16
#define KK 8192
#define NN 8192
#define GROUPK 128
#define SPLITK 16
#define KC     512             // k per block (= KPER)
#define NTILE  128             // columns per block (4 warps x 32 cols)
#define WARPS  4
#define NTHREADS (WARPS * 32)
#define NCB    (NN / NTILE)    // 64 column-blocks
#define ROUNDS (KC / 32)       // 16 rounds of 32-k
#define R4STRIDE  (NN)         // int4 units between rounds (4 rows * NN ints / 4)
#define SCSTRIDE  (NN / 4)     // float4 units per scale-group row

// x pre-converted to fp16 in A-fragment order: [ks*16+r][j][lane] uint4
__device__ uint4 g_xfrag[256 * 2 * 32];             // 256 KB

__device__ __forceinline__ uint32_t lop3_ea(uint32_t v, uint32_t m, uint32_t o) {
    uint32_t h;
    asm("lop3.b32 %0, %1, %2, %3, 0xEA;" : "=r"(h) : "r"(v), "r"(m), "r"(o));
    return h;   // (v & m) | o
}

__device__ __forceinline__ uint32_t packh2(float a, float b) {
    half2 h = __floats2half2_rn(a, b);
    return *reinterpret_cast<uint32_t*>(&h);
}

// streaming (evict-first) 16B load: keeps the qweight stream out of L1's way
__device__ __forceinline__ uint4 ldcs16(const int4* p) {
    uint4 v;
    asm volatile("ld.global.cs.v4.u32 {%0,%1,%2,%3}, [%4];"
                 : "=r"(v.x), "=r"(v.y), "=r"(v.z), "=r"(v.w) : "l"(p));
    return v;
}

__device__ __forceinline__ void mma16816(float* c,
                                         uint32_t a0, uint32_t a1, uint32_t a2, uint32_t a3,
                                         uint32_t b0, uint32_t b1) {
    asm volatile(
        "mma.sync.aligned.m16n8k16.row.col.f32.f16.f16.f32 "
        "{%0,%1,%2,%3}, {%4,%5,%6,%7}, {%8,%9}, {%0,%1,%2,%3};\n"
        : "+f"(c[0]), "+f"(c[1]), "+f"(c[2]), "+f"(c[3])
        : "r"(a0), "r"(a1), "r"(a2), "r"(a3), "r"(b0), "r"(b1));
}

// Marlin-mask dequant: pairs (0,4)/(2,6) via 0x000F000F -> (h-1032);
// pairs (1,5)/(3,7) via 0x00F000F0 (=1024+16n) -> fma(h,1/16,-72) = n-8 EXACT.
// Then fp16 scale multiply (single rounding = reference w). 1 SHF instead of 3.
__device__ __forceinline__ void procj(float* acc, uint32_t wj, half2 s,
                                      const uint4& va, const uint4& vb,
                                      half2 c1032, half2 rcp16, half2 cm72) {
    uint32_t t = wj >> 8;
    uint32_t h00 = lop3_ea(wj, 0x000F000Fu, 0x64006400u);   // (n0,n4): 1024+n
    uint32_t h01 = lop3_ea(wj, 0x00F000F0u, 0x64006400u);   // (n1,n5): 1024+16n
    uint32_t h02 = lop3_ea(t,  0x000F000Fu, 0x64006400u);   // (n2,n6)
    uint32_t h03 = lop3_ea(t,  0x00F000F0u, 0x64006400u);   // (n3,n7)
    half2 w00 = __hsub2(*reinterpret_cast<half2*>(&h00), c1032);
    half2 w01 = __hfma2(*reinterpret_cast<half2*>(&h01), rcp16, cm72);
    half2 w02 = __hsub2(*reinterpret_cast<half2*>(&h02), c1032);
    half2 w03 = __hfma2(*reinterpret_cast<half2*>(&h03), rcp16, cm72);
    half2 b00 = __hmul2(w00, s), b01 = __hmul2(w01, s);
    half2 b02 = __hmul2(w02, s), b03 = __hmul2(w03, s);
    mma16816(acc, va.x, va.y, va.z, va.w,
             *reinterpret_cast<uint32_t*>(&b00), *reinterpret_cast<uint32_t*>(&b01));
    mma16816(acc, vb.x, vb.y, vb.z, vb.w,
             *reinterpret_cast<uint32_t*>(&b02), *reinterpret_cast<uint32_t*>(&b03));
}

// no-return vectorized f32 reduction into global (sm_90+)
__device__ __forceinline__ void redg_v4(float* p, float a, float b, float c, float d) {
    asm volatile("red.global.add.v4.f32 [%0], {%1, %2, %3, %4};"
                 :: "l"(p), "f"(a), "f"(b), "f"(c), "f"(d) : "memory");
}

// Combo front kernel: blocks 0-31 convert x into A-fragment order;
// blocks 32-95 initialize out with broadcast f32(f16(bias)) (clears poison).
__global__ void __launch_bounds__(256)
prep_combo(const float* __restrict__ x, const float* __restrict__ bias,
           float* __restrict__ out)
{
    int tid = threadIdx.x;
    if (blockIdx.x < 32) {
        int t = blockIdx.x * 256 + tid;               // 0..8191
        int rem = t & 31;
        int rg  = t >> 5;                             // ks*16 + r
        int g   = rem >> 2;
        int ii  = rem & 3;
        int b   = rg * 32 + ii * 8;
        const float* xlo = x + (size_t)g       * KK + b;
        const float* xhi = x + (size_t)(g + 8) * KK + b;
        float4 l0 = *reinterpret_cast<const float4*>(xlo);
        float4 l1 = *reinterpret_cast<const float4*>(xlo + 4);
        float4 h0 = *reinterpret_cast<const float4*>(xhi);
        float4 h1 = *reinterpret_cast<const float4*>(xhi + 4);
        uint4 e0, e1;
        e0.x = packh2(l0.x, l1.x);   // (b+0, b+4) row g     -> a0 of mma j=0
        e0.y = packh2(h0.x, h1.x);   //            row g+8   -> a1
        e0.z = packh2(l0.y, l1.y);   // (b+1, b+5)           -> a2
        e0.w = packh2(h0.y, h1.y);   //                      -> a3
        e1.x = packh2(l0.z, l1.z);   // (b+2, b+6)           -> mma j=1
        e1.y = packh2(h0.z, h1.z);
        e1.z = packh2(l0.w, l1.w);   // (b+3, b+7)
        e1.w = packh2(h0.w, h1.w);
        g_xfrag[rg * 64 + rem]      = e0;
        g_xfrag[rg * 64 + 32 + rem] = e1;
    } else {
        // init: 16384 threads x 2 float4 = 32768 float4 = all of out
        int i = (blockIdx.x - 32) * 256 + tid;        // 0..16383
        int n4 = i & (NN / 4 - 1);                    // same column set for both rows
        const float4 bv = *reinterpret_cast<const float4*>(bias + n4 * 4);
        float4 o;
        o.x = __half2float(__float2half_rn(bv.x));    // f32(f16(bias)) as in reference
        o.y = __half2float(__float2half_rn(bv.y));
        o.z = __half2float(__float2half_rn(bv.z));
        o.w = __half2float(__float2half_rn(bv.w));
        float4* out4 = reinterpret_cast<float4*>(out);
        out4[i]         = o;
        out4[i + 16384] = o;                          // +8 rows
    }
}

// Smem-free GEMM with atomic-reduce epilogue. 8 blocks/SM (64 regs, full RF).
// Lane (g8,i4) loads int4 = cols colbase+4*g8+{0..3} of packed row 4r+i4
// (coalesced 128B, streaming/evict-first); MMA group j uses col set
// {colbase+4n+j} (undone in epilogue indexing). qweight + xfrag register-
// prefetched rolling depth-2; scales double-buffered one full group ahead.
__global__ void __launch_bounds__(NTHREADS, 8)
qlinear_gemm(const int* __restrict__ qweight, const float* __restrict__ scales,
             float* __restrict__ out)
{
    const int tid  = threadIdx.x;
    const int lane = tid & 31;
    const int warp = tid >> 5;
    const int ks   = blockIdx.y;
    const int cb   = blockIdx.x;
    const int colbase = cb * NTILE + warp * 32;
    const int i4 = lane & 3;   // threadID_in_group
    const int g8 = lane >> 2;  // groupID

    const half2 c1032 = __half2half2(__ushort_as_half((unsigned short)0x6408)); // 1032.0
    const half2 rcp16 = __half2half2(__ushort_as_half((unsigned short)0x2C00)); // 1/16
    const half2 cm72  = __half2half2(__ushort_as_half((unsigned short)0xD480)); // -72.0

    // qweight: packed rows [ks*64 .. ks*64+63]; lane reads row (4r+i4), cols colbase+4*g8..+3
    const int4* qp = reinterpret_cast<const int4*>(
        qweight + (size_t)(ks * 64 + i4) * NN + colbase) + g8;
    // scales: group rows [ks*4 .. ks*4+3]; lane reads cols colbase+4*g8..+3 (B-fragment coords)
    const float4* scp = reinterpret_cast<const float4*>(
        scales + (size_t)(ks * 4) * NN + colbase) + g8;
    // A fragments for this ks
    const uint4* xf = g_xfrag + (size_t)(ks * ROUNDS) * 64 + lane;

    float accm[4][4] = {};
    uint4 wqbuf[2], vaf[2], vbf[2];    // rolling depth-2 round prefetch
    float4 sfb;                        // next-group scales, loaded one group early

    wqbuf[0] = ldcs16(qp);
    wqbuf[1] = ldcs16(qp + R4STRIDE);
    vaf[0] = xf[0];       vbf[0] = xf[32];
    vaf[1] = xf[64];      vbf[1] = xf[96];
    sfb = __ldg(scp);                  // group 0 scales

    #pragma unroll
    for (int r4 = 0; r4 < 4; ++r4) {               // 4 scale-groups of 128 k
        half2 hs[4];
        hs[0] = __half2half2(__float2half_rn(sfb.x));
        hs[1] = __half2half2(__float2half_rn(sfb.y));
        hs[2] = __half2half2(__float2half_rn(sfb.z));
        hs[3] = __half2half2(__float2half_rn(sfb.w));
        if (r4 < 3)                                 // prefetch next group's scales (~1600 cyc early)
            sfb = __ldg(scp + (size_t)(r4 + 1) * SCSTRIDE);
        #pragma unroll
        for (int rr = 0; rr < 4; ++rr) {           // 4 rounds = 128 k
            int r = r4 * 4 + rr;
            uint4 w  = wqbuf[r & 1];
            uint4 va = vaf[r & 1];
            uint4 vb = vbf[r & 1];
            if (r + 2 < ROUNDS) {                  // rolling prefetch, distance 2
                wqbuf[r & 1] = ldcs16(qp + (size_t)(r + 2) * R4STRIDE);
                vaf[r & 1]   = xf[(r + 2) * 64];
                vbf[r & 1]   = xf[(r + 2) * 64 + 32];
            }
            procj(accm[0], w.x, hs[0], va, vb, c1032, rcp16, cm72);
            procj(accm[1], w.y, hs[1], va, vb, c1032, rcp16, cm72);
            procj(accm[2], w.z, hs[2], va, vb, c1032, rcp16, cm72);
            procj(accm[3], w.w, hs[3], va, vb, c1032, rcp16, cm72);
        }
    }

    // ---- atomic-reduce fp32 partials into out (bias pre-added by init).
    // group j's C col = colbase + 8*i4 + j (rows g8, g8+8); +4 for c[1]/c[3].
    {
        float* op = out + (size_t)g8 * NN + colbase + 8 * i4;
        redg_v4(op,     accm[0][0], accm[1][0], accm[2][0], accm[3][0]);
        redg_v4(op + 4, accm[0][1], accm[1][1], accm[2][1], accm[3][1]);
        float* op2 = op + (size_t)8 * NN;
        redg_v4(op2,     accm[0][2], accm[1][2], accm[2][2], accm[3][2]);
        redg_v4(op2 + 4, accm[0][3], accm[1][3], accm[2][3], accm[3][3]);
    }
}

extern "C" void kernel_launch(void* const* d_in, const int* in_sizes, int n_in,
                              void* d_out, int out_size) {
    // identify inputs by unique element counts (robust to ordering)
    const float* x = nullptr; const int* qw = nullptr;
    const float* sc = nullptr; const float* bias = nullptr;
    for (int i = 0; i < n_in; ++i) {
        switch (in_sizes[i]) {
            case MM * KK:              x    = (const float*)d_in[i]; break;  // 131072
            case (KK / 8) * NN:        qw   = (const int*)  d_in[i]; break;  // 8388608
            case (KK / GROUPK) * NN:   sc   = (const float*)d_in[i]; break;  // 524288
            case NN:                   bias = (const float*)d_in[i]; break;  // 8192
        }
    }
    float* out = (float*)d_out;

    prep_combo<<<96, 256>>>(x, bias, out);     // x-permute + out-init (bias)

    dim3 grid(NCB, SPLITK);                    // 64 x 16 = 1024 blocks, 8/SM wave
    qlinear_gemm<<<grid, NTHREADS>>>(qw, sc, out);
}